// round 12
// baseline (speedup 1.0000x reference)
#include <cuda_runtime.h>
#include <math.h>

#define NN 8
#define CC 80
#define PP 15200           // H*W
#define PF4 3800           // PP/4
#define PCE 1216000        // C*P
#define PC4 (PCE/4)
#define NBINS 4096
#define CAP 16384
#define MAXSEL 8192
#define TOPK 1000
#define OUTK 100
#define PRE_TH 0.05f
#define RAW_LO -2.945f     // conservative logit(0.05)
#define NMS_TH 0.6f
#define COFF 100000.0f

// -------- static scratch (no allocations allowed) --------
__device__ float4             g_pm4[NN * 4 * PF4];   // partial channel maxes (4 splits)
__device__ float4             g_ctr4[NN * PF4];      // exact centerness sigmoid
__device__ int                g_pts[NN * PP];        // selected point ids
__device__ int                g_npts[NN];
__device__ float              g_thrF[NN];            // score threshold (cut bin lower edge)
__device__ float              g_thrc[NN];            // raw-logit prescreen for gather
__device__ int                g_cnt[NN];
__device__ unsigned           g_chist[NN * NBINS];   // exact candidate-score histogram
__device__ unsigned long long g_cand[NN * CAP];
__device__ float4             g_box[NN * TOPK];
__device__ float4             g_obox[NN * TOPK];
__device__ float              g_area[NN * TOPK];
__device__ float              g_sc[NN * TOPK];
__device__ int                g_lab[NN * TOPK];
__device__ int                g_nv[NN];
__device__ unsigned           g_mask[NN * TOPK * 32];

extern __shared__ unsigned long long dynsmem[];

__device__ __forceinline__ float sigm_exact(float x) { return 1.0f / (1.0f + expf(-x)); }

// K1: the ONLY full pass over box_cls — per-point max over a 20-channel split
__global__ void k_max(const float4* __restrict__ cls4) {
    int img = blockIdx.z, z = blockIdx.y;
    int q = blockIdx.x * 256 + threadIdx.x;
    if (q >= PF4) return;
    const float4* c = cls4 + (long)img * PC4 + (long)(z * 20) * PF4 + q;
    float4 m = c[0];
#pragma unroll
    for (int ch = 1; ch < 20; ch++) {
        float4 v = c[ch * PF4];
        m.x = fmaxf(m.x, v.x); m.y = fmaxf(m.y, v.y);
        m.z = fmaxf(m.z, v.z); m.w = fmaxf(m.w, v.w);
    }
    g_pm4[(img * 4 + z) * PF4 + q] = m;
}

// K2: per-image point screening via per-point max candidate score upper bound
__global__ void k_points(const float4* __restrict__ ctr4) {
    __shared__ unsigned s[NBINS];
    __shared__ int scut, snp;
    int img = blockIdx.x;
    int tid = threadIdx.x;  // 1024
    for (int b = tid; b < NBINS; b += 1024) { s[b] = 0u; g_chist[img * NBINS + b] = 0u; }
    if (tid == 0) { scut = 0; snp = 0; g_cnt[img] = 0; }
    __syncthreads();

    float u_loc[4][4];
#pragma unroll
    for (int it = 0; it < 4; it++) {
        int t = tid + it * 1024;
        if (t < PF4) {
            float4 a = g_pm4[(img * 4 + 0) * PF4 + t];
            float4 b = g_pm4[(img * 4 + 1) * PF4 + t];
            float4 c = g_pm4[(img * 4 + 2) * PF4 + t];
            float4 d = g_pm4[(img * 4 + 3) * PF4 + t];
            float4 ct = ctr4[img * PF4 + t];
            float mm[4] = { fmaxf(fmaxf(a.x, b.x), fmaxf(c.x, d.x)),
                            fmaxf(fmaxf(a.y, b.y), fmaxf(c.y, d.y)),
                            fmaxf(fmaxf(a.z, b.z), fmaxf(c.z, d.z)),
                            fmaxf(fmaxf(a.w, b.w), fmaxf(c.w, d.w)) };
            float cs[4] = { sigm_exact(ct.x), sigm_exact(ct.y),
                            sigm_exact(ct.z), sigm_exact(ct.w) };
            g_ctr4[img * PF4 + t] = make_float4(cs[0], cs[1], cs[2], cs[3]);
#pragma unroll
            for (int l = 0; l < 4; l++) {
                float sm = sigm_exact(mm[l]);
                float u = (sm > PRE_TH) ? sm * cs[l] : 0.0f;
                u_loc[it][l] = u;
                if (u > 0.0f) atomicAdd(&s[__float_as_uint(u) >> 18], 1u);
            }
        } else {
#pragma unroll
            for (int l = 0; l < 4; l++) u_loc[it][l] = 0.0f;
        }
    }
    __syncthreads();

    // suffix scan over 4096 bins (4 bins per thread)
    for (int d = 1; d < NBINS; d <<= 1) {
        unsigned t0 = s[tid]        + ((tid + d        < NBINS) ? s[tid + d]        : 0u);
        unsigned t1 = s[tid + 1024] + ((tid + 1024 + d < NBINS) ? s[tid + 1024 + d] : 0u);
        unsigned t2 = s[tid + 2048] + ((tid + 2048 + d < NBINS) ? s[tid + 2048 + d] : 0u);
        unsigned t3 = s[tid + 3072] + ((tid + 3072 + d < NBINS) ? s[tid + 3072 + d] : 0u);
        __syncthreads();
        s[tid] = t0; s[tid + 1024] = t1; s[tid + 2048] = t2; s[tid + 3072] = t3;
        __syncthreads();
    }
#pragma unroll
    for (int q = 0; q < 4; q++) {
        int b = tid + q * 1024;
        if (s[b] >= TOPK && (b == NBINS - 1 || s[b + 1] < TOPK)) scut = b;
    }
    __syncthreads();

    int cb = scut;
    float thrF = __uint_as_float((unsigned)cb << 18);          // gather threshold (<= s_1000)
    float thrP = (cb > 0) ? __uint_as_float((unsigned)(cb - 1) << 18) : 0.0f;
    if (tid == 0) {
        g_thrF[img] = thrF;
        float thrc = RAW_LO;
        if (thrF > 0.0f && thrF < 1.0f)
            thrc = fmaxf(logf(thrF / (1.0f - thrF)) - 1e-3f, RAW_LO);
        g_thrc[img] = thrc;
    }

    // compact surviving points
#pragma unroll
    for (int it = 0; it < 4; it++) {
        int t = tid + it * 1024;
        if (t < PF4) {
#pragma unroll
            for (int l = 0; l < 4; l++) {
                float u = u_loc[it][l];
                if (u > 0.0f && u >= thrP) {
                    int sl = atomicAdd(&snp, 1);
                    g_pts[img * PP + sl] = 4 * t + l;
                }
            }
        }
    }
    __syncthreads();
    if (tid == 0) g_npts[img] = snp;
}

// K3: gather candidates from selected points; build EXACT candidate-score histogram
__global__ void k_gather(const float* __restrict__ cls) {
    int img = blockIdx.y;
    int npts = g_npts[img];
    float thrF = g_thrF[img];
    float thrc = g_thrc[img];
    const float* c = cls + (long)img * PCE;
    const float* ctrs = (const float*)g_ctr4 + img * PP;
    int stride = gridDim.x * blockDim.x;
    for (int ip = blockIdx.x * blockDim.x + threadIdx.x; ip < npts; ip += stride) {
        int p = g_pts[img * PP + ip];
        float sctr = ctrs[p];
        for (int ch0 = 0; ch0 < CC; ch0 += 8) {
            float v[8];
#pragma unroll
            for (int j = 0; j < 8; j++) v[j] = c[(ch0 + j) * PP + p];
#pragma unroll
            for (int j = 0; j < 8; j++) {
                float x = v[j];
                if (x > thrc) {
                    float sm = sigm_exact(x);
                    if (sm > PRE_TH) {
                        float sc = sm * sctr;
                        if (sc >= thrF) {
                            int pos = atomicAdd(&g_cnt[img], 1);
                            if (pos < CAP) {
                                unsigned u = __float_as_uint(sc);
                                atomicAdd(&g_chist[img * NBINS + (u >> 18)], 1u);
                                unsigned idx = (unsigned)(p * CC + ch0 + j);
                                g_cand[img * CAP + pos] =
                                    ((unsigned long long)(~u) << 32) | (unsigned long long)idx;
                            }
                        }
                    }
                }
            }
        }
    }
}

// K4: exact rank-TOPK pre-selection, then small bitonic sort + box decode
__global__ void k_sort(const float* __restrict__ regs, const float* __restrict__ locs,
                       const float* __restrict__ info) {
    unsigned long long* keys = dynsmem;                 // MAXSEL
    unsigned* s = (unsigned*)(keys + MAXSEL);           // NBINS
    __shared__ int scb, scnt;
    int img = blockIdx.x;
    int tid = threadIdx.x;  // 1024
    int n = g_cnt[img]; if (n > CAP) n = CAP;
    for (int b = tid; b < NBINS; b += 1024) s[b] = g_chist[img * NBINS + b];
    if (tid == 0) { scb = 0; scnt = 0; }
    __syncthreads();
    // suffix scan of exact candidate hist
    for (int d = 1; d < NBINS; d <<= 1) {
        unsigned t0 = s[tid]        + ((tid + d        < NBINS) ? s[tid + d]        : 0u);
        unsigned t1 = s[tid + 1024] + ((tid + 1024 + d < NBINS) ? s[tid + 1024 + d] : 0u);
        unsigned t2 = s[tid + 2048] + ((tid + 2048 + d < NBINS) ? s[tid + 2048 + d] : 0u);
        unsigned t3 = s[tid + 3072] + ((tid + 3072 + d < NBINS) ? s[tid + 3072 + d] : 0u);
        __syncthreads();
        s[tid] = t0; s[tid + 1024] = t1; s[tid + 2048] = t2; s[tid + 3072] = t3;
        __syncthreads();
    }
#pragma unroll
    for (int q = 0; q < 4; q++) {
        int b = tid + q * 1024;
        if (s[b] >= TOPK && (b == NBINS - 1 || s[b + 1] < TOPK)) scb = b;
    }
    __syncthreads();
    int cb = scb;
    while (cb < NBINS - 1 && s[cb] > MAXSEL) cb++;      // overflow guard (practically never)
    // load only candidates in bins >= cb (superset of exact top-1000, ties included)
    for (int t = tid; t < n; t += 1024) {
        unsigned long long e = g_cand[img * CAP + t];
        unsigned u = ~((unsigned)(e >> 32));
        if ((int)(u >> 18) >= cb) {
            int pos = atomicAdd(&scnt, 1);
            if (pos < MAXSEL) keys[pos] = e;
        }
    }
    __syncthreads();
    int m = scnt; if (m > MAXSEL) m = MAXSEL;
    int n2 = 1; while (n2 < m) n2 <<= 1;
    for (int t = m + tid; t < n2; t += 1024) keys[t] = ~0ULL;
    __syncthreads();
    for (int k = 2; k <= n2; k <<= 1)
        for (int j = k >> 1; j > 0; j >>= 1) {
            for (int i = tid; i < n2; i += 1024) {
                int l = i ^ j;
                if (l > i) {
                    unsigned long long a = keys[i], b = keys[l];
                    bool asc = ((i & k) == 0);
                    if ((a > b) == asc) { keys[i] = b; keys[l] = a; }
                }
            }
            __syncthreads();
        }
    if (tid < TOPK) {
        int t = tid;
        bool valid = (t < m);
        float4 bx = make_float4(0.f, 0.f, 0.f, 0.f);
        float4 ob = make_float4(0.f, 0.f, 0.f, 0.f);
        float sv = 0.f, ar = 0.f; int lab = 0;
        if (valid) {
            unsigned long long e = keys[t];
            unsigned u = ~((unsigned)(e >> 32));
            unsigned idx = (unsigned)e;
            sv = __uint_as_float(u);
            int loc = (int)(idx / CC);
            lab = (int)(idx % CC) + 1;
            const float* rg = regs + (long)img * 4 * PP;
            float rl = rg[loc], rt = rg[PP + loc], rr = rg[2 * PP + loc], rb = rg[3 * PP + loc];
            float px = locs[2 * loc], py = locs[2 * loc + 1];
            float him = info[img * 2], wim = info[img * 2 + 1];
            float x1 = fminf(fmaxf(px - rl, 0.f), wim - 1.f);
            float y1 = fminf(fmaxf(py - rt, 0.f), him - 1.f);
            float x2 = fminf(fmaxf(px + rr, 0.f), wim - 1.f);
            float y2 = fminf(fmaxf(py + rb, 0.f), him - 1.f);
            bx = make_float4(x1, y1, x2, y2);
            float off = (float)lab * COFF;
            ob = make_float4(x1 + off, y1 + off, x2 + off, y2 + off);
            ar = fmaxf(ob.z - ob.x, 0.f) * fmaxf(ob.w - ob.y, 0.f);
        }
        g_box[img * TOPK + t]  = bx;
        g_obox[img * TOPK + t] = ob;
        g_area[img * TOPK + t] = ar;
        g_sc[img * TOPK + t]   = sv;
        g_lab[img * TOPK + t]  = lab;
    }
    if (tid == 0) g_nv[img] = (m < TOPK) ? m : TOPK;
}

// K5: suppression bit-matrix (1000 rows x 32 words), reference-exact IoU on offset boxes
__global__ void k_iou() {
    __shared__ float4 sob[1024];
    __shared__ float  sar[1024];
    int img = blockIdx.y;
    for (int t = threadIdx.x; t < 1024; t += 256) {
        if (t < TOPK) { sob[t] = g_obox[img * TOPK + t]; sar[t] = g_area[img * TOPK + t]; }
        else          { sob[t] = make_float4(0.f, 0.f, 0.f, 0.f); sar[t] = 0.f; }
    }
    __syncthreads();
    int item = blockIdx.x * 256 + threadIdx.x;
    if (item >= TOPK * 32) return;
    int i = item >> 5, w = item & 31;
    float4 bi = sob[i]; float ai = sar[i];
    unsigned bits = 0u;
    int jbase = w * 32;
#pragma unroll
    for (int b = 0; b < 32; b++) {
        int j = jbase + b;
        if (j > i && j < TOPK) {
            float4 bj = sob[j];
            float lx = fmaxf(bi.x, bj.x), ly = fmaxf(bi.y, bj.y);
            float rx = fminf(bi.z, bj.z), ry = fminf(bi.w, bj.w);
            float iw = fmaxf(rx - lx, 0.f), ih = fmaxf(ry - ly, 0.f);
            float inter = iw * ih;
            float iou = inter / (ai + sar[j] - inter + 1e-9f);
            if (iou > NMS_TH) bits |= (1u << b);
        }
    }
    g_mask[(img * TOPK + i) * 32 + w] = bits;
}

// K6: greedy NMS via find-next-clear-bit (ffs + warp min-reduce), early exit at 100
__global__ void k_nms(float* __restrict__ out) {
    unsigned* smk = (unsigned*)dynsmem;  // TOPK*32 words
    __shared__ int skeep[OUTK];
    __shared__ int sfound;
    int img = blockIdx.x;
    int tid = threadIdx.x;  // 1024
    for (int t = tid; t < TOPK * 32; t += 1024) smk[t] = g_mask[img * TOPK * 32 + t];
    __syncthreads();
    if (tid < 32) {
        int lane = tid;
        int nv = g_nv[img];
        int lo = lane * 32;
        unsigned skip;
        if (lo >= nv)            skip = 0xFFFFFFFFu;
        else if (lo + 32 <= nv)  skip = 0u;
        else                     skip = 0xFFFFFFFFu << (nv - lo);
        int found = 0;
        while (found < OUTK) {
            unsigned avail = ~skip;
            int local = __ffs(avail);                       // 1-based, 0 if none
            int cand = local ? (lane * 32 + local - 1) : 0x7FFFFFFF;
            int i = __reduce_min_sync(0xFFFFFFFFu, cand);
            if (i == 0x7FFFFFFF) break;
            if (lane == 0) skeep[found] = i;
            found++;
            if (lane == (i >> 5)) skip |= (1u << (i & 31)); // consume i
            if (found >= OUTK) break;
            skip |= smk[i * 32 + lane];                     // suppress row i
        }
        if (lane == 0) sfound = found;
    }
    __syncthreads();
    if (tid < OUTK * 6) {
        int r = tid / 6, k = tid % 6;
        float v = 0.f;
        if (r < sfound) {
            int i = skeep[r];
            if (k < 4)      v = ((const float*)g_box)[(img * TOPK + i) * 4 + k];
            else if (k == 4) v = (float)g_lab[img * TOPK + i];
            else            v = g_sc[img * TOPK + i];
        }
        out[img * OUTK * 6 + tid] = v;
    }
}

extern "C" void kernel_launch(void* const* d_in, const int* in_sizes, int n_in,
                              void* d_out, int out_size) {
    const float* locs = (const float*)d_in[0];   // [P,2]
    const float* cls  = (const float*)d_in[1];   // [N,C,H,W]
    const float* regs = (const float*)d_in[2];   // [N,4,H,W]
    const float* ctr  = (const float*)d_in[3];   // [N,1,H,W]
    const float* info = (const float*)d_in[4];   // [N,2]
    float* out = (float*)d_out;                  // [N,100,6]

    cudaFuncSetAttribute(k_sort, cudaFuncAttributeMaxDynamicSharedMemorySize,
                         MAXSEL * 8 + NBINS * 4);
    cudaFuncSetAttribute(k_nms,  cudaFuncAttributeMaxDynamicSharedMemorySize, TOPK * 32 * 4);

    k_max<<<dim3((PF4 + 255) / 256, 4, NN), 256>>>((const float4*)cls);
    k_points<<<NN, 1024>>>((const float4*)ctr);
    k_gather<<<dim3(8, NN), 256>>>(cls);
    k_sort<<<NN, 1024, MAXSEL * 8 + NBINS * 4>>>(regs, locs, info);
    k_iou<<<dim3((TOPK * 32 + 255) / 256, NN), 256>>>();
    k_nms<<<NN, 1024, TOPK * 32 * 4>>>(out);
}

// round 17
// speedup vs baseline: 1.1087x; 1.1087x over previous
#include <cuda_runtime.h>
#include <math.h>

#define NN 8
#define CC 80
#define PP 15200           // H*W
#define PF4 3800           // PP/4
#define PCE 1216000        // C*P
#define PC4 (PCE/4)
#define NBINS 4096
#define CAP 16384
#define SELCAP 2048
#define TOPK 1000
#define OUTK 100
#define PRE_TH 0.05f
#define RAW_LO -2.945f     // conservative logit(0.05)
#define NMS_TH 0.6f
#define COFF 100000.0f

// -------- static scratch (no allocations allowed) --------
__device__ float4             g_pm4[NN * 4 * PF4];   // partial channel maxes (4 splits)
__device__ float4             g_ctr4[NN * PF4];      // exact centerness sigmoid
__device__ int                g_pts[NN * PP];        // selected point ids
__device__ int                g_npts[NN];
__device__ float              g_thrF[NN];            // score threshold (cut bin lower edge)
__device__ float              g_thrc[NN];            // raw-logit prescreen for gather
__device__ int                g_cnt[NN];
__device__ unsigned           g_chist[NN * NBINS];   // exact candidate-score histogram
__device__ unsigned long long g_cand[NN * CAP];
__device__ float4             g_box[NN * TOPK];
__device__ float4             g_obox[NN * TOPK];
__device__ float              g_area[NN * TOPK];
__device__ float              g_sc[NN * TOPK];
__device__ int                g_lab[NN * TOPK];
__device__ int                g_nv[NN];
__device__ unsigned           g_mask[NN * TOPK * 32];

extern __shared__ unsigned long long dynsmem[];

__device__ __forceinline__ float sigm_exact(float x) { return 1.0f / (1.0f + expf(-x)); }

// 3-barrier suffix scan over 4096 shared bins (1024 threads, 4 bins/thread).
// On exit h[b] = sum_{b' >= b} h_in[b'].
__device__ __forceinline__ void suffix4096(unsigned* h) {
    __shared__ unsigned wsum[32];
    __shared__ unsigned wexc[32];
    int tid = threadIdx.x, lane = tid & 31, wp = tid >> 5;
    int b0 = tid * 4;
    unsigned v0 = h[b0], v1 = h[b0 + 1], v2 = h[b0 + 2], v3 = h[b0 + 3];
    unsigned s3 = v3, s2 = v2 + s3, s1 = v1 + s2, s0 = v0 + s1;
    unsigned tot = s0, x = tot;
#pragma unroll
    for (int off = 1; off < 32; off <<= 1) {
        unsigned y = __shfl_down_sync(0xFFFFFFFFu, x, off);
        if (lane + off < 32) x += y;
    }
    if (lane == 0) wsum[wp] = x;           // warp total (sum of its 128 bins)
    __syncthreads();
    if (wp == 0) {
        unsigned wx = wsum[lane], xx = wx;
#pragma unroll
        for (int off = 1; off < 32; off <<= 1) {
            unsigned y = __shfl_down_sync(0xFFFFFFFFu, xx, off);
            if (lane + off < 32) xx += y;
        }
        wexc[lane] = xx - wx;              // sum of warps above
    }
    __syncthreads();
    unsigned base = wexc[wp] + (x - tot);  // higher warps + higher lanes in warp
    h[b0] = s0 + base; h[b0 + 1] = s1 + base; h[b0 + 2] = s2 + base; h[b0 + 3] = s3 + base;
    __syncthreads();
}

// K1: the ONLY full pass over box_cls — per-point max over a 20-channel split
__global__ void k_max(const float4* __restrict__ cls4) {
    int img = blockIdx.z, z = blockIdx.y;
    int q = blockIdx.x * 256 + threadIdx.x;
    if (q >= PF4) return;
    const float4* c = cls4 + (long)img * PC4 + (long)(z * 20) * PF4 + q;
    float4 m = c[0];
#pragma unroll
    for (int ch = 1; ch < 20; ch++) {
        float4 v = c[ch * PF4];
        m.x = fmaxf(m.x, v.x); m.y = fmaxf(m.y, v.y);
        m.z = fmaxf(m.z, v.z); m.w = fmaxf(m.w, v.w);
    }
    g_pm4[(img * 4 + z) * PF4 + q] = m;
}

// K2: per-image point screening via per-point max candidate score upper bound
__global__ void k_points(const float4* __restrict__ ctr4) {
    __shared__ unsigned s[NBINS];
    __shared__ int scut, snp;
    int img = blockIdx.x;
    int tid = threadIdx.x;  // 1024
#pragma unroll
    for (int q = 0; q < 4; q++) { s[tid + q * 1024] = 0u; g_chist[img * NBINS + tid + q * 1024] = 0u; }
    if (tid == 0) { scut = 0; snp = 0; g_cnt[img] = 0; }
    __syncthreads();

    float u_loc[4][4];
#pragma unroll
    for (int it = 0; it < 4; it++) {
        int t = tid + it * 1024;
        if (t < PF4) {
            float4 a = g_pm4[(img * 4 + 0) * PF4 + t];
            float4 b = g_pm4[(img * 4 + 1) * PF4 + t];
            float4 c = g_pm4[(img * 4 + 2) * PF4 + t];
            float4 d = g_pm4[(img * 4 + 3) * PF4 + t];
            float4 ct = ctr4[img * PF4 + t];
            float mm[4] = { fmaxf(fmaxf(a.x, b.x), fmaxf(c.x, d.x)),
                            fmaxf(fmaxf(a.y, b.y), fmaxf(c.y, d.y)),
                            fmaxf(fmaxf(a.z, b.z), fmaxf(c.z, d.z)),
                            fmaxf(fmaxf(a.w, b.w), fmaxf(c.w, d.w)) };
            float cs[4] = { sigm_exact(ct.x), sigm_exact(ct.y),
                            sigm_exact(ct.z), sigm_exact(ct.w) };
            g_ctr4[img * PF4 + t] = make_float4(cs[0], cs[1], cs[2], cs[3]);
#pragma unroll
            for (int l = 0; l < 4; l++) {
                float sm = sigm_exact(mm[l]);
                float u = (sm > PRE_TH) ? sm * cs[l] : 0.0f;
                u_loc[it][l] = u;
                if (u > 0.0f) atomicAdd(&s[__float_as_uint(u) >> 18], 1u);
            }
        } else {
#pragma unroll
            for (int l = 0; l < 4; l++) u_loc[it][l] = 0.0f;
        }
    }
    __syncthreads();

    suffix4096(s);
#pragma unroll
    for (int q = 0; q < 4; q++) {
        int b = tid * 4 + q;
        unsigned sb = s[b];
        unsigned sb1 = (b == NBINS - 1) ? 0u : s[b + 1];
        if (sb >= TOPK && sb1 < TOPK) scut = b;
    }
    __syncthreads();

    int cb = scut;
    float thrF = __uint_as_float((unsigned)cb << 18);          // gather threshold (<= s_1000)
    float thrP = (cb > 0) ? __uint_as_float((unsigned)(cb - 1) << 18) : 0.0f;
    if (tid == 0) {
        g_thrF[img] = thrF;
        float thrc = RAW_LO;
        if (thrF > 0.0f && thrF < 1.0f)
            thrc = fmaxf(logf(thrF / (1.0f - thrF)) - 1e-3f, RAW_LO);
        g_thrc[img] = thrc;
    }

    // compact surviving points
#pragma unroll
    for (int it = 0; it < 4; it++) {
        int t = tid + it * 1024;
        if (t < PF4) {
#pragma unroll
            for (int l = 0; l < 4; l++) {
                float u = u_loc[it][l];
                if (u > 0.0f && u >= thrP) {
                    int sl = atomicAdd(&snp, 1);
                    g_pts[img * PP + sl] = 4 * t + l;
                }
            }
        }
    }
    __syncthreads();
    if (tid == 0) g_npts[img] = snp;
}

// K3: gather candidates from selected points; build EXACT candidate-score histogram
__global__ void k_gather(const float* __restrict__ cls) {
    int img = blockIdx.y;
    int npts = g_npts[img];
    float thrF = g_thrF[img];
    float thrc = g_thrc[img];
    const float* c = cls + (long)img * PCE;
    const float* ctrs = (const float*)g_ctr4 + img * PP;
    int stride = gridDim.x * blockDim.x;
    for (int ip = blockIdx.x * blockDim.x + threadIdx.x; ip < npts; ip += stride) {
        int p = g_pts[img * PP + ip];
        float sctr = ctrs[p];
        for (int ch0 = 0; ch0 < CC; ch0 += 8) {
            float v[8];
#pragma unroll
            for (int j = 0; j < 8; j++) v[j] = c[(ch0 + j) * PP + p];
#pragma unroll
            for (int j = 0; j < 8; j++) {
                float x = v[j];
                if (x > thrc) {
                    float sm = sigm_exact(x);
                    if (sm > PRE_TH) {
                        float sc = sm * sctr;
                        if (sc >= thrF) {
                            int pos = atomicAdd(&g_cnt[img], 1);
                            if (pos < CAP) {
                                unsigned u = __float_as_uint(sc);
                                atomicAdd(&g_chist[img * NBINS + (u >> 18)], 1u);
                                unsigned idx = (unsigned)(p * CC + ch0 + j);
                                g_cand[img * CAP + pos] =
                                    ((unsigned long long)(~u) << 32) | (unsigned long long)idx;
                            }
                        }
                    }
                }
            }
        }
    }
}

// K4: exact rank-TOPK pre-selection + hybrid register/shfl bitonic (2048) + decode
__global__ void k_sort(const float* __restrict__ regs, const float* __restrict__ locs,
                       const float* __restrict__ info) {
    __shared__ unsigned long long skeys[SELCAP];
    __shared__ unsigned sh[NBINS];
    __shared__ int scb, scnt;
    int img = blockIdx.x;
    int tid = threadIdx.x;  // 1024
    int n = g_cnt[img]; if (n > CAP) n = CAP;
#pragma unroll
    for (int q = 0; q < 4; q++) sh[tid + q * 1024] = g_chist[img * NBINS + tid + q * 1024];
    if (tid == 0) { scb = 0; scnt = 0; }
    __syncthreads();
    suffix4096(sh);
#pragma unroll
    for (int q = 0; q < 4; q++) {
        int b = tid * 4 + q;
        unsigned sb = sh[b];
        unsigned sb1 = (b == NBINS - 1) ? 0u : sh[b + 1];
        if (sb >= TOPK && sb1 < TOPK) scb = b;
    }
    __syncthreads();
    int cb = scb;
    while (cb < NBINS - 1 && sh[cb] > SELCAP) cb++;   // overflow guard (ties; practically never)
    // select candidates in bins >= cb (superset of exact top-1000, ties included)
    for (int t = tid; t < n; t += 1024) {
        unsigned long long e = g_cand[img * CAP + t];
        unsigned u = ~((unsigned)(e >> 32));
        if ((int)(u >> 18) >= cb) {
            int pos = atomicAdd(&scnt, 1);
            if (pos < SELCAP) skeys[pos] = e;
        }
    }
    __syncthreads();
    int m = scnt; if (m > SELCAP) m = SELCAP;
    if (tid >= m)        skeys[tid] = ~0ULL;
    if (tid + 1024 >= m) skeys[tid + 1024] = ~0ULL;
    __syncthreads();

    // ---- hybrid bitonic sort of 2048 keys (ascending = score desc, idx asc) ----
    unsigned long long r0 = skeys[tid], r1 = skeys[tid + 1024];
    // k = 2..32: pure register/shfl stages (no barriers)
#pragma unroll
    for (int k = 2; k <= 32; k <<= 1) {
#pragma unroll
        for (int j = k >> 1; j >= 1; j >>= 1) {
            bool asc = ((tid & k) == 0);               // same for both elements (k<=32)
            bool low = ((tid & j) == 0);
            bool km = (low == asc);
            unsigned long long p0 = __shfl_xor_sync(0xFFFFFFFFu, r0, j);
            unsigned long long p1 = __shfl_xor_sync(0xFFFFFFFFu, r1, j);
            r0 = km ? (r0 < p0 ? r0 : p0) : (r0 > p0 ? r0 : p0);
            r1 = km ? (r1 < p1 ? r1 : p1) : (r1 > p1 ? r1 : p1);
        }
    }
    skeys[tid] = r0; skeys[tid + 1024] = r1;
    __syncthreads();
    // k = 64..2048: smem stages for j>=32, register/shfl for j<=16
#pragma unroll
    for (int k = 64; k <= 2048; k <<= 1) {
#pragma unroll
        for (int j = k >> 1; j >= 32; j >>= 1) {
#pragma unroll
            for (int rr = 0; rr < 2; rr++) {
                int i = tid + rr * 1024;
                int l = i ^ j;
                if (l > i) {
                    unsigned long long a = skeys[i], b = skeys[l];
                    bool asc = ((i & k) == 0);
                    if ((a > b) == asc) { skeys[i] = b; skeys[l] = a; }
                }
            }
            __syncthreads();
        }
        r0 = skeys[tid]; r1 = skeys[tid + 1024];
        bool asc0 = ((tid & k) == 0);
        bool asc1 = (((tid + 1024) & k) == 0);
#pragma unroll
        for (int j = 16; j >= 1; j >>= 1) {
            bool low = ((tid & j) == 0);
            bool km0 = (low == asc0), km1 = (low == asc1);
            unsigned long long p0 = __shfl_xor_sync(0xFFFFFFFFu, r0, j);
            unsigned long long p1 = __shfl_xor_sync(0xFFFFFFFFu, r1, j);
            r0 = km0 ? (r0 < p0 ? r0 : p0) : (r0 > p0 ? r0 : p0);
            r1 = km1 ? (r1 < p1 ? r1 : p1) : (r1 > p1 ? r1 : p1);
        }
        skeys[tid] = r0; skeys[tid + 1024] = r1;
        __syncthreads();
    }

    if (tid < TOPK) {
        int t = tid;
        bool valid = (t < m);
        float4 bx = make_float4(0.f, 0.f, 0.f, 0.f);
        float4 ob = make_float4(0.f, 0.f, 0.f, 0.f);
        float sv = 0.f, ar = 0.f; int lab = 0;
        if (valid) {
            unsigned long long e = skeys[t];
            unsigned u = ~((unsigned)(e >> 32));
            unsigned idx = (unsigned)e;
            sv = __uint_as_float(u);
            int loc = (int)(idx / CC);
            lab = (int)(idx % CC) + 1;
            const float* rg = regs + (long)img * 4 * PP;
            float rl = rg[loc], rt = rg[PP + loc], rr = rg[2 * PP + loc], rb = rg[3 * PP + loc];
            float px = locs[2 * loc], py = locs[2 * loc + 1];
            float him = info[img * 2], wim = info[img * 2 + 1];
            float x1 = fminf(fmaxf(px - rl, 0.f), wim - 1.f);
            float y1 = fminf(fmaxf(py - rt, 0.f), him - 1.f);
            float x2 = fminf(fmaxf(px + rr, 0.f), wim - 1.f);
            float y2 = fminf(fmaxf(py + rb, 0.f), him - 1.f);
            bx = make_float4(x1, y1, x2, y2);
            float off = (float)lab * COFF;
            ob = make_float4(x1 + off, y1 + off, x2 + off, y2 + off);
            ar = fmaxf(ob.z - ob.x, 0.f) * fmaxf(ob.w - ob.y, 0.f);
        }
        g_box[img * TOPK + t]  = bx;
        g_obox[img * TOPK + t] = ob;
        g_area[img * TOPK + t] = ar;
        g_sc[img * TOPK + t]   = sv;
        g_lab[img * TOPK + t]  = lab;
    }
    if (tid == 0) g_nv[img] = (m < TOPK) ? m : TOPK;
}

// K5: suppression bit-matrix (1000 rows x 32 words), reference-exact IoU on offset boxes
__global__ void k_iou() {
    __shared__ float4 sob[1024];
    __shared__ float  sar[1024];
    int img = blockIdx.y;
    for (int t = threadIdx.x; t < 1024; t += 256) {
        if (t < TOPK) { sob[t] = g_obox[img * TOPK + t]; sar[t] = g_area[img * TOPK + t]; }
        else          { sob[t] = make_float4(0.f, 0.f, 0.f, 0.f); sar[t] = 0.f; }
    }
    __syncthreads();
    int item = blockIdx.x * 256 + threadIdx.x;
    if (item >= TOPK * 32) return;
    int i = item >> 5, w = item & 31;
    float4 bi = sob[i]; float ai = sar[i];
    unsigned bits = 0u;
    int jbase = w * 32;
#pragma unroll
    for (int b = 0; b < 32; b++) {
        int j = jbase + b;
        if (j > i && j < TOPK) {
            float4 bj = sob[j];
            float lx = fmaxf(bi.x, bj.x), ly = fmaxf(bi.y, bj.y);
            float rx = fminf(bi.z, bj.z), ry = fminf(bi.w, bj.w);
            float iw = fmaxf(rx - lx, 0.f), ih = fmaxf(ry - ly, 0.f);
            float inter = iw * ih;
            float iou = inter / (ai + sar[j] - inter + 1e-9f);
            if (iou > NMS_TH) bits |= (1u << b);
        }
    }
    g_mask[(img * TOPK + i) * 32 + w] = bits;
}

// K6: greedy NMS via find-next-clear-bit (ffs + warp min-reduce), early exit at 100
__global__ void k_nms(float* __restrict__ out) {
    unsigned* smk = (unsigned*)dynsmem;  // TOPK*32 words
    __shared__ int skeep[OUTK];
    __shared__ int sfound;
    int img = blockIdx.x;
    int tid = threadIdx.x;  // 1024
    for (int t = tid; t < TOPK * 32; t += 1024) smk[t] = g_mask[img * TOPK * 32 + t];
    __syncthreads();
    if (tid < 32) {
        int lane = tid;
        int nv = g_nv[img];
        int lo = lane * 32;
        unsigned skip;
        if (lo >= nv)            skip = 0xFFFFFFFFu;
        else if (lo + 32 <= nv)  skip = 0u;
        else                     skip = 0xFFFFFFFFu << (nv - lo);
        int found = 0;
        while (found < OUTK) {
            unsigned avail = ~skip;
            int local = __ffs(avail);                       // 1-based, 0 if none
            int cand = local ? (lane * 32 + local - 1) : 0x7FFFFFFF;
            int i = __reduce_min_sync(0xFFFFFFFFu, cand);
            if (i == 0x7FFFFFFF) break;
            if (lane == 0) skeep[found] = i;
            found++;
            if (lane == (i >> 5)) skip |= (1u << (i & 31)); // consume i
            if (found >= OUTK) break;
            skip |= smk[i * 32 + lane];                     // suppress row i
        }
        if (lane == 0) sfound = found;
    }
    __syncthreads();
    if (tid < OUTK * 6) {
        int r = tid / 6, k = tid % 6;
        float v = 0.f;
        if (r < sfound) {
            int i = skeep[r];
            if (k < 4)      v = ((const float*)g_box)[(img * TOPK + i) * 4 + k];
            else if (k == 4) v = (float)g_lab[img * TOPK + i];
            else            v = g_sc[img * TOPK + i];
        }
        out[img * OUTK * 6 + tid] = v;
    }
}

extern "C" void kernel_launch(void* const* d_in, const int* in_sizes, int n_in,
                              void* d_out, int out_size) {
    const float* locs = (const float*)d_in[0];   // [P,2]
    const float* cls  = (const float*)d_in[1];   // [N,C,H,W]
    const float* regs = (const float*)d_in[2];   // [N,4,H,W]
    const float* ctr  = (const float*)d_in[3];   // [N,1,H,W]
    const float* info = (const float*)d_in[4];   // [N,2]
    float* out = (float*)d_out;                  // [N,100,6]

    cudaFuncSetAttribute(k_nms, cudaFuncAttributeMaxDynamicSharedMemorySize, TOPK * 32 * 4);

    k_max<<<dim3((PF4 + 255) / 256, 4, NN), 256>>>((const float4*)cls);
    k_points<<<NN, 1024>>>((const float4*)ctr);
    k_gather<<<dim3(8, NN), 256>>>(cls);
    k_sort<<<NN, 1024>>>(regs, locs, info);
    k_iou<<<dim3((TOPK * 32 + 255) / 256, NN), 256>>>();
    k_nms<<<NN, 1024, TOPK * 32 * 4>>>(out);
}